// round 13
// baseline (speedup 1.0000x reference)
#include <cuda_runtime.h>
#include <cuda.h>
#include <cuda_fp16.h>
#include <cstdint>

// ---------------------------------------------------------------------------
// Problem dims
// ---------------------------------------------------------------------------
#define M_DIM 8192
#define N_DIM 11008
#define K_DIM 4096

#define BM 128
#define BN 256
#define BK 64                      // 64 fp16 = 128B row = SW128 atom
#define STAGES 4
#define KTILES (K_DIM / BK)        // 64
#define CLUSTER_M 4
#define NTILES (N_DIM / BN)        // 43
#define MTILES (M_DIM / BM)        // 64

#define NWARPS_C 16                // consumer warps (4 per SMSP)
#define NTHREADS (NWARPS_C * 32 + 32)   // 544

// SMEM layout
#define SMEM_A_STAGE 16384
#define SMEM_B_STAGE 32768
#define SMEM_B_SLICE 8192
#define SMEM_A_OFF 0
#define SMEM_B_OFF (STAGES * SMEM_A_STAGE)               // 65536
#define BAR_OFF (SMEM_B_OFF + STAGES * SMEM_B_STAGE)     // 196608
#define SMEM_TOTAL (BAR_OFF + 128)
#define STAGE_TX (SMEM_A_STAGE + SMEM_B_STAGE)           // 49152

// Device-global scratch
__device__ __half g_x[(size_t)M_DIM * K_DIM];
__device__ __half g_deq[(size_t)N_DIM * K_DIM];
__device__ int    g_flags;   // bit0: x/out fp32, bit1: w int32, bit2: s fp32

// ---------------------------------------------------------------------------
// PTX helpers
// ---------------------------------------------------------------------------
__device__ __forceinline__ uint32_t smem_u32(const void* p) {
    return (uint32_t)__cvta_generic_to_shared(p);
}
__device__ __forceinline__ uint32_t elect_one() {
    uint32_t pred;
    asm volatile("{\n\t.reg .pred p;\n\telect.sync _|p, 0xFFFFFFFF;\n\t"
                 "selp.b32 %0, 1, 0, p;\n\t}" : "=r"(pred));
    return pred;
}
__device__ __forceinline__ uint32_t ctarank() {
    uint32_t r; asm("mov.u32 %0, %%cluster_ctarank;" : "=r"(r)); return r;
}
__device__ __forceinline__ void mbar_init(uint32_t a, uint32_t n) {
    asm volatile("mbarrier.init.shared.b64 [%0], %1;" :: "r"(a), "r"(n) : "memory");
}
__device__ __forceinline__ void mbar_expect_tx(uint32_t a, uint32_t b) {
    asm volatile("mbarrier.arrive.expect_tx.shared.b64 _, [%0], %1;" :: "r"(a), "r"(b) : "memory");
}
__device__ __forceinline__ void mbar_wait(uint32_t a, uint32_t parity) {
    asm volatile("{\n\t.reg .pred P;\n\t"
                 "W_%=:\n\t"
                 "mbarrier.try_wait.parity.acquire.cta.shared::cta.b64 P, [%0], %1, 0x989680;\n\t"
                 "@P bra.uni D_%=;\n\t"
                 "bra.uni W_%=;\n\t"
                 "D_%=:\n\t}" :: "r"(a), "r"(parity) : "memory");
}
__device__ __forceinline__ void mbar_wait_relaxed(uint32_t a, uint32_t parity) {
    asm volatile("{\n\t.reg .pred P;\n\t"
                 "W_%=:\n\t"
                 "mbarrier.try_wait.parity.relaxed.cta.shared::cta.b64 P, [%0], %1, 0x989680;\n\t"
                 "@P bra.uni D_%=;\n\t"
                 "bra.uni W_%=;\n\t"
                 "D_%=:\n\t}" :: "r"(a), "r"(parity) : "memory");
}
__device__ __forceinline__ void mbar_arrive_cluster(uint32_t local_addr, uint32_t rank) {
    asm volatile("{\n\t.reg .b32 ra;\n\t"
                 "mapa.shared::cluster.u32 ra, %0, %1;\n\t"
                 "mbarrier.arrive.shared::cluster.b64 _, [ra];\n\t}"
                 :: "r"(local_addr), "r"(rank) : "memory");
}
__device__ __forceinline__ void tma_load(uint32_t dst, const void* map, int x, int y,
                                         uint32_t mbar) {
    asm volatile("cp.async.bulk.tensor.3d.shared::cta.global.tile.mbarrier::complete_tx::bytes "
                 "[%0], [%1, {%2, %3, %4}], [%5];"
                 :: "r"(dst), "l"(map), "r"(x), "r"(y), "r"(0), "r"(mbar) : "memory");
}
__device__ __forceinline__ void tma_load_mc(uint32_t dst, const void* map, int x, int y,
                                            uint32_t mbar, uint16_t mask) {
    asm volatile("cp.async.bulk.tensor.3d.shared::cluster.global.tile."
                 "mbarrier::complete_tx::bytes.multicast::cluster "
                 "[%0], [%1, {%2, %3, %4}], [%5], %6;"
                 :: "r"(dst), "l"(map), "r"(x), "r"(y), "r"(0), "r"(mbar), "h"(mask) : "memory");
}
__device__ __forceinline__ void cluster_sync() {
    asm volatile("barrier.cluster.arrive.aligned;" ::: "memory");
    asm volatile("barrier.cluster.wait.aligned;" ::: "memory");
}
__device__ __forceinline__ void ldsm4(uint32_t& r0, uint32_t& r1,
                                      uint32_t& r2, uint32_t& r3, uint32_t sa) {
    asm volatile("ldmatrix.sync.aligned.m8n8.x4.shared.b16 {%0,%1,%2,%3}, [%4];\n"
                 : "=r"(r0), "=r"(r1), "=r"(r2), "=r"(r3) : "r"(sa));
}
__device__ __forceinline__ void mma16816(float* c, const uint32_t* a, const uint32_t* b) {
    asm volatile("mma.sync.aligned.m16n8k16.row.col.f32.f16.f16.f32 "
                 "{%0,%1,%2,%3}, {%4,%5,%6,%7}, {%8,%9}, {%0,%1,%2,%3};\n"
                 : "+f"(c[0]), "+f"(c[1]), "+f"(c[2]), "+f"(c[3])
                 : "r"(a[0]), "r"(a[1]), "r"(a[2]), "r"(a[3]),
                   "r"(b[0]), "r"(b[1]));
}
#define SW128(b) ((b) ^ (((b) >> 3) & 0x70))

// ---------------------------------------------------------------------------
// Dtype detection (proven)
// ---------------------------------------------------------------------------
__global__ void detect_kernel(const unsigned int* __restrict__ xw,
                              const unsigned int* __restrict__ ww,
                              const unsigned int* __restrict__ sw) {
    __shared__ int cx, cw, cs;
    if (threadIdx.x == 0) { cx = 0; cw = 0; cs = 0; }
    __syncthreads();
    unsigned int vx = xw[threadIdx.x];
    unsigned int vw = ww[threadIdx.x];
    unsigned int vs = sw[threadIdx.x];
    if ((vx & 0x1FFFu) == 0u) atomicAdd(&cx, 1);
    unsigned int t = vw >> 8;
    if (t == 0u || t == 0x00FFFFFFu) atomicAdd(&cw, 1);
    if ((vs & 0x1FFFu) == 0u) atomicAdd(&cs, 1);
    __syncthreads();
    if (threadIdx.x == 0) {
        int f = 0;
        if (cx >= 120) f |= 1;
        if (cw >= 120) f |= 2;
        if (cs >= 120) f |= 4;
        g_flags = f;
    }
}

// ---------------------------------------------------------------------------
// x -> fp16 funnel (R9 version, proven)
// ---------------------------------------------------------------------------
__global__ void convert_x_kernel(const void* __restrict__ xp) {
    const int flags = g_flags;
    size_t t = (size_t)blockIdx.x * blockDim.x + threadIdx.x;
    __align__(16) __half out[8];
    if (flags & 1) {
        const float4* p = (const float4*)xp;
        float4 f0 = p[t * 2], f1 = p[t * 2 + 1];
        out[0] = __float2half(f0.x); out[1] = __float2half(f0.y);
        out[2] = __float2half(f0.z); out[3] = __float2half(f0.w);
        out[4] = __float2half(f1.x); out[5] = __float2half(f1.y);
        out[6] = __float2half(f1.z); out[7] = __float2half(f1.w);
    } else {
        *reinterpret_cast<uint4*>(out) = reinterpret_cast<const uint4*>(xp)[t];
    }
    *reinterpret_cast<uint4*>(&g_x[t * 8]) = *reinterpret_cast<const uint4*>(out);
}

// ---------------------------------------------------------------------------
// Q4_0 dequant (R9 version, proven)
// ---------------------------------------------------------------------------
__global__ void dequant_kernel(const void* __restrict__ wp,
                               const void* __restrict__ sp) {
    const int flags = g_flags;
    int t = blockIdx.x * blockDim.x + threadIdx.x;
    int i      = t >> 9;
    int jp     = t & 511;
    int jg     = jp >> 3;
    int within = (jp & 7) << 3;

    size_t elem = (size_t)(i * 32 + (jg >> 1)) * 64 + within;

    unsigned char bytes[8];
    if (flags & 2) {
        const int4* pi = reinterpret_cast<const int4*>((const int*)wp + elem);
        int4 a = pi[0], b = pi[1];
        bytes[0] = (unsigned char)a.x; bytes[1] = (unsigned char)a.y;
        bytes[2] = (unsigned char)a.z; bytes[3] = (unsigned char)a.w;
        bytes[4] = (unsigned char)b.x; bytes[5] = (unsigned char)b.y;
        bytes[6] = (unsigned char)b.z; bytes[7] = (unsigned char)b.w;
    } else {
        *reinterpret_cast<uint2*>(bytes) =
            *reinterpret_cast<const uint2*>((const signed char*)wp + elem);
    }

    float scale = (flags & 4) ? ((const float*)sp)[i * 64 + jg]
                              : __half2float(((const __half*)sp)[i * 64 + jg]);
    bool hi = (jg & 1) == 0;

    __align__(16) __half out[8];
#pragma unroll
    for (int b = 0; b < 8; b++) {
        signed char sc = (signed char)bytes[b];
        int v;
        if (hi) v = sc >> 4;
        else    v = (sc & 15) - ((sc & 8) << 1);
        out[b] = __float2half(v * scale);
    }
    *reinterpret_cast<uint4*>(&g_deq[(size_t)i * K_DIM + ((size_t)jp << 3)]) =
        *reinterpret_cast<const uint4*>(out);
}

// ---------------------------------------------------------------------------
// GEMM: grid (43, 64), cluster (1,4,1). 544 threads.
//   warps 0-15: mma.sync consumers (warp tile 32x64), B-fragment double
//               buffering: LDSM(ks+1) issued before MMA(ks) so shared-memory
//               latency overlaps tensor execution.
//   warp 16:    TMA producer (A per-CTA, B slice multicast).
// ---------------------------------------------------------------------------
__global__ void __launch_bounds__(NTHREADS, 1) gemm_tc(
    const __grid_constant__ CUtensorMap tmapA,
    const __grid_constant__ CUtensorMap tmapB,
    void* __restrict__ y)
{
    extern __shared__ char smem[];
    const uint32_t sb   = smem_u32(smem);
    const int tid  = threadIdx.x;
    const int lane = tid & 31;
    const int warp = tid >> 5;
    const uint32_t rank = ctarank();
    const int ntile = blockIdx.x;
    const int mtile = blockIdx.y;

    const uint32_t full0  = sb + BAR_OFF;
    const uint32_t empty0 = sb + BAR_OFF + 32;

    if (tid == 0) {
#pragma unroll
        for (int s = 0; s < STAGES; s++) {
            mbar_init(full0 + s * 8, 1);
            mbar_init(empty0 + s * 8, NWARPS_C * CLUSTER_M);
        }
    }
    __syncthreads();
    cluster_sync();

    if (warp == NWARPS_C) {
        // ---------------- TMA producer ----------------
        if (elect_one()) {
            int stage = 0, phase = 1;
            for (int kt = 0; kt < KTILES; kt++) {
                mbar_wait_relaxed(empty0 + stage * 8, phase);
                uint32_t fb = full0 + stage * 8;
                mbar_expect_tx(fb, STAGE_TX);
                tma_load(sb + SMEM_A_OFF + stage * SMEM_A_STAGE, &tmapA,
                         kt * BK, mtile * BM, fb);
                tma_load_mc(sb + SMEM_B_OFF + stage * SMEM_B_STAGE + rank * SMEM_B_SLICE,
                            &tmapB, kt * BK, ntile * BN + (int)rank * 64, fb, 0xF);
                if (++stage == STAGES) { stage = 0; phase ^= 1; }
            }
        }
    } else {
        // ---------------- consumers ----------------
        const int wm = warp & 3;    // 32 rows each
        const int wn = warp >> 2;   // 64 cols each

        float acc[2][8][4];
#pragma unroll
        for (int i = 0; i < 2; i++)
#pragma unroll
            for (int j = 0; j < 8; j++)
#pragma unroll
                for (int k = 0; k < 4; k++) acc[i][j][k] = 0.f;

        // per-thread ldmatrix byte-offset bases (within a stage tile)
        const int a_off0 = (wm * 32 + (lane & 15)) * 128 + (((lane >> 4) << 3) << 1);
        const int b_off0 = (wn * 64 + (lane & 7) + ((lane >> 4) << 3)) * 128
                         + ((((lane >> 3) & 1) << 3) << 1);

        int stage = 0, phase = 0;
        for (int kt = 0; kt < KTILES; kt++) {
            mbar_wait(full0 + stage * 8, phase);
            const uint32_t a_base = sb + SMEM_A_OFF + stage * SMEM_A_STAGE;
            const uint32_t b_base = sb + SMEM_B_OFF + stage * SMEM_B_STAGE;

            // B fragment double buffer: prefetch ks+1 while MMA(ks) runs
            uint32_t bfr[2][4][4];
#pragma unroll
            for (int ni2 = 0; ni2 < 4; ni2++) {
                int byte = b_off0 + ni2 * 2048;        // ks = 0
                ldsm4(bfr[0][ni2][0], bfr[0][ni2][1], bfr[0][ni2][2], bfr[0][ni2][3],
                      b_base + SW128(byte));
            }

#pragma unroll
            for (int ks = 0; ks < 4; ks++) {
                const int cur = ks & 1;
                if (ks < 3) {
                    const int nxt = cur ^ 1;
#pragma unroll
                    for (int ni2 = 0; ni2 < 4; ni2++) {
                        int byte = b_off0 + ni2 * 2048 + (ks + 1) * 32;
                        ldsm4(bfr[nxt][ni2][0], bfr[nxt][ni2][1],
                              bfr[nxt][ni2][2], bfr[nxt][ni2][3],
                              b_base + SW128(byte));
                    }
                }
                // A just-in-time (small burst; covered by 4-warp interleave)
                uint32_t a[2][4];
#pragma unroll
                for (int mi = 0; mi < 2; mi++) {
                    int byte = a_off0 + mi * 2048 + ks * 32;
                    ldsm4(a[mi][0], a[mi][1], a[mi][2], a[mi][3], a_base + SW128(byte));
                }
                if (ks == 3) {
                    if (elect_one()) {
#pragma unroll
                        for (int r = 0; r < CLUSTER_M; r++)
                            mbar_arrive_cluster(empty0 + stage * 8, r);
                    }
                }
#pragma unroll
                for (int mi = 0; mi < 2; mi++)
#pragma unroll
                    for (int ni = 0; ni < 8; ni++)
                        mma16816(acc[mi][ni], a[mi], &bfr[cur][ni >> 1][(ni & 1) * 2]);
            }
            if (++stage == STAGES) { stage = 0; phase ^= 1; }
        }

        // ---------------- epilogue ----------------
        const int flags = g_flags;
        const size_t base_m = (size_t)mtile * BM + wm * 32;
        const int base_n = ntile * BN + wn * 64;
#pragma unroll
        for (int mi = 0; mi < 2; mi++) {
            size_t m0 = base_m + mi * 16 + (lane >> 2);
#pragma unroll
            for (int ni = 0; ni < 8; ni++) {
                int n = base_n + ni * 8 + (lane & 3) * 2;
                __half h0 = __float2half(acc[mi][ni][0]);
                __half h1 = __float2half(acc[mi][ni][1]);
                __half h2 = __float2half(acc[mi][ni][2]);
                __half h3 = __float2half(acc[mi][ni][3]);
                if (flags & 1) {
                    float* yf = (float*)y;
                    *reinterpret_cast<float2*>(yf + m0 * N_DIM + n) =
                        make_float2(__half2float(h0), __half2float(h1));
                    *reinterpret_cast<float2*>(yf + (m0 + 8) * N_DIM + n) =
                        make_float2(__half2float(h2), __half2float(h3));
                } else {
                    __half* yh = (__half*)y;
                    *reinterpret_cast<__half2*>(yh + m0 * N_DIM + n) =
                        __halves2half2(h0, h1);
                    *reinterpret_cast<__half2*>(yh + (m0 + 8) * N_DIM + n) =
                        __halves2half2(h2, h3);
                }
            }
        }
    }

    cluster_sync();
}

// ---------------------------------------------------------------------------
// kernel_launch — inputs by element count: x=33,554,432 w=22,544,384 s=704,512
// ---------------------------------------------------------------------------
typedef CUresult (*EncodeFn)(CUtensorMap*, CUtensorMapDataType, cuuint32_t, void*,
                             const cuuint64_t*, const cuuint64_t*, const cuuint32_t*,
                             const cuuint32_t*, CUtensorMapInterleave, CUtensorMapSwizzle,
                             CUtensorMapL2promotion, CUtensorMapFloatOOBfill);

extern "C" void kernel_launch(void* const* d_in, const int* in_sizes, int n_in,
                              void* d_out, int out_size) {
    const void* x = nullptr; const void* w = nullptr; const void* s = nullptr;
    for (int i = 0; i < n_in; i++) {
        if      (in_sizes[i] == 33554432) x = d_in[i];
        else if (in_sizes[i] == 22544384) w = d_in[i];
        else if (in_sizes[i] == 704512)   s = d_in[i];
    }

    detect_kernel<<<1, 128>>>((const unsigned int*)x, (const unsigned int*)w,
                              (const unsigned int*)s);
    convert_x_kernel<<<16384, 256>>>(x);
    dequant_kernel<<<22016, 256>>>(w, s);

    static CUtensorMap tA, tB;
    static bool built = false;
    if (!built) {
        void* encode_raw = nullptr;
        cudaDriverEntryPointQueryResult qr;
        cudaGetDriverEntryPointByVersion("cuTensorMapEncodeTiled", &encode_raw, 12000,
                                         cudaEnableDefault, &qr);
        EncodeFn encode = (EncodeFn)encode_raw;
        void* pa = nullptr; void* pb = nullptr;
        cudaGetSymbolAddress(&pa, g_x);
        cudaGetSymbolAddress(&pb, g_deq);

        cuuint64_t dA[3] = {K_DIM, M_DIM, 1};
        cuuint64_t sA[2] = {K_DIM * 2ull, (cuuint64_t)K_DIM * M_DIM * 2ull};
        cuuint32_t bA[3] = {BK, BM, 1};
        cuuint32_t eS[3] = {1, 1, 1};
        encode(&tA, CU_TENSOR_MAP_DATA_TYPE_FLOAT16, 3, pa, dA, sA, bA, eS,
               CU_TENSOR_MAP_INTERLEAVE_NONE, CU_TENSOR_MAP_SWIZZLE_128B,
               CU_TENSOR_MAP_L2_PROMOTION_L2_128B, CU_TENSOR_MAP_FLOAT_OOB_FILL_NONE);

        cuuint64_t dB[3] = {K_DIM, N_DIM, 1};
        cuuint64_t sB[2] = {K_DIM * 2ull, (cuuint64_t)K_DIM * N_DIM * 2ull};
        cuuint32_t bB[3] = {BK, 64, 1};
        encode(&tB, CU_TENSOR_MAP_DATA_TYPE_FLOAT16, 3, pb, dB, sB, bB, eS,
               CU_TENSOR_MAP_INTERLEAVE_NONE, CU_TENSOR_MAP_SWIZZLE_128B,
               CU_TENSOR_MAP_L2_PROMOTION_L2_128B, CU_TENSOR_MAP_FLOAT_OOB_FILL_NONE);

        cudaFuncSetAttribute(gemm_tc, cudaFuncAttributeMaxDynamicSharedMemorySize,
                             SMEM_TOTAL);
        built = true;
    }

    cudaLaunchConfig_t cfg = {};
    cfg.gridDim  = {NTILES, MTILES, 1};
    cfg.blockDim = {NTHREADS, 1, 1};
    cfg.dynamicSmemBytes = SMEM_TOTAL;
    cfg.stream = 0;
    cudaLaunchAttribute attrs[1];
    attrs[0].id = cudaLaunchAttributeClusterDimension;
    attrs[0].val.clusterDim = {1, CLUSTER_M, 1};
    cfg.attrs = attrs;
    cfg.numAttrs = 1;
    cudaLaunchKernelEx(&cfg, gemm_tc, tA, tB, d_out);
}

// round 14
// speedup vs baseline: 1.0383x; 1.0383x over previous
#include <cuda_runtime.h>
#include <cuda.h>
#include <cuda_fp16.h>
#include <cstdint>

// ---------------------------------------------------------------------------
// Problem dims
// ---------------------------------------------------------------------------
#define M_DIM 8192
#define N_DIM 11008
#define K_DIM 4096

#define BM 128
#define BN 256
#define BK 64                      // 64 fp16 = 128B row = SW128 atom
#define STAGES 4
#define KTILES (K_DIM / BK)        // 64
#define CLUSTER_M 4
#define NTILES (N_DIM / BN)        // 43
#define MTILES (M_DIM / BM)        // 64

#define NWARPS_C 16                // consumer warps (4 per SMSP)
#define NTHREADS (NWARPS_C * 32 + 32)   // 544

// SMEM layout
#define SMEM_A_STAGE 16384
#define SMEM_B_STAGE 32768
#define SMEM_B_SLICE 8192
#define SMEM_A_OFF 0
#define SMEM_B_OFF (STAGES * SMEM_A_STAGE)               // 65536
#define BAR_OFF (SMEM_B_OFF + STAGES * SMEM_B_STAGE)     // 196608
#define SMEM_TOTAL (BAR_OFF + 128)
#define STAGE_TX (SMEM_A_STAGE + SMEM_B_STAGE)           // 49152

// Device-global scratch
__device__ __half g_x[(size_t)M_DIM * K_DIM];
__device__ __half g_deq[(size_t)N_DIM * K_DIM];
__device__ int    g_flags;   // bit0: x/out fp32, bit1: w int32, bit2: s fp32

// ---------------------------------------------------------------------------
// PTX helpers
// ---------------------------------------------------------------------------
__device__ __forceinline__ uint32_t smem_u32(const void* p) {
    return (uint32_t)__cvta_generic_to_shared(p);
}
__device__ __forceinline__ uint32_t elect_one() {
    uint32_t pred;
    asm volatile("{\n\t.reg .pred p;\n\telect.sync _|p, 0xFFFFFFFF;\n\t"
                 "selp.b32 %0, 1, 0, p;\n\t}" : "=r"(pred));
    return pred;
}
__device__ __forceinline__ uint32_t ctarank() {
    uint32_t r; asm("mov.u32 %0, %%cluster_ctarank;" : "=r"(r)); return r;
}
__device__ __forceinline__ void mbar_init(uint32_t a, uint32_t n) {
    asm volatile("mbarrier.init.shared.b64 [%0], %1;" :: "r"(a), "r"(n) : "memory");
}
__device__ __forceinline__ void mbar_expect_tx(uint32_t a, uint32_t b) {
    asm volatile("mbarrier.arrive.expect_tx.shared.b64 _, [%0], %1;" :: "r"(a), "r"(b) : "memory");
}
__device__ __forceinline__ void mbar_wait(uint32_t a, uint32_t parity) {
    asm volatile("{\n\t.reg .pred P;\n\t"
                 "W_%=:\n\t"
                 "mbarrier.try_wait.parity.acquire.cta.shared::cta.b64 P, [%0], %1, 0x989680;\n\t"
                 "@P bra.uni D_%=;\n\t"
                 "bra.uni W_%=;\n\t"
                 "D_%=:\n\t}" :: "r"(a), "r"(parity) : "memory");
}
__device__ __forceinline__ void mbar_wait_relaxed(uint32_t a, uint32_t parity) {
    asm volatile("{\n\t.reg .pred P;\n\t"
                 "W_%=:\n\t"
                 "mbarrier.try_wait.parity.relaxed.cta.shared::cta.b64 P, [%0], %1, 0x989680;\n\t"
                 "@P bra.uni D_%=;\n\t"
                 "bra.uni W_%=;\n\t"
                 "D_%=:\n\t}" :: "r"(a), "r"(parity) : "memory");
}
__device__ __forceinline__ void mbar_arrive_cluster(uint32_t local_addr, uint32_t rank) {
    asm volatile("{\n\t.reg .b32 ra;\n\t"
                 "mapa.shared::cluster.u32 ra, %0, %1;\n\t"
                 "mbarrier.arrive.shared::cluster.b64 _, [ra];\n\t}"
                 :: "r"(local_addr), "r"(rank) : "memory");
}
__device__ __forceinline__ void tma_load(uint32_t dst, const void* map, int x, int y,
                                         uint32_t mbar) {
    asm volatile("cp.async.bulk.tensor.3d.shared::cta.global.tile.mbarrier::complete_tx::bytes "
                 "[%0], [%1, {%2, %3, %4}], [%5];"
                 :: "r"(dst), "l"(map), "r"(x), "r"(y), "r"(0), "r"(mbar) : "memory");
}
__device__ __forceinline__ void tma_load_mc(uint32_t dst, const void* map, int x, int y,
                                            uint32_t mbar, uint16_t mask) {
    asm volatile("cp.async.bulk.tensor.3d.shared::cluster.global.tile."
                 "mbarrier::complete_tx::bytes.multicast::cluster "
                 "[%0], [%1, {%2, %3, %4}], [%5], %6;"
                 :: "r"(dst), "l"(map), "r"(x), "r"(y), "r"(0), "r"(mbar), "h"(mask) : "memory");
}
__device__ __forceinline__ void cluster_sync() {
    asm volatile("barrier.cluster.arrive.aligned;" ::: "memory");
    asm volatile("barrier.cluster.wait.aligned;" ::: "memory");
}
__device__ __forceinline__ void ldsm4(uint32_t& r0, uint32_t& r1,
                                      uint32_t& r2, uint32_t& r3, uint32_t sa) {
    asm volatile("ldmatrix.sync.aligned.m8n8.x4.shared.b16 {%0,%1,%2,%3}, [%4];\n"
                 : "=r"(r0), "=r"(r1), "=r"(r2), "=r"(r3) : "r"(sa));
}
__device__ __forceinline__ void mma16816(float* c, const uint32_t* a, const uint32_t* b) {
    asm volatile("mma.sync.aligned.m16n8k16.row.col.f32.f16.f16.f32 "
                 "{%0,%1,%2,%3}, {%4,%5,%6,%7}, {%8,%9}, {%0,%1,%2,%3};\n"
                 : "+f"(c[0]), "+f"(c[1]), "+f"(c[2]), "+f"(c[3])
                 : "r"(a[0]), "r"(a[1]), "r"(a[2]), "r"(a[3]),
                   "r"(b[0]), "r"(b[1]));
}
#define SW128(b) ((b) ^ (((b) >> 3) & 0x70))

// ---------------------------------------------------------------------------
// Dtype detection (proven)
// ---------------------------------------------------------------------------
__global__ void detect_kernel(const unsigned int* __restrict__ xw,
                              const unsigned int* __restrict__ ww,
                              const unsigned int* __restrict__ sw) {
    __shared__ int cx, cw, cs;
    if (threadIdx.x == 0) { cx = 0; cw = 0; cs = 0; }
    __syncthreads();
    unsigned int vx = xw[threadIdx.x];
    unsigned int vw = ww[threadIdx.x];
    unsigned int vs = sw[threadIdx.x];
    if ((vx & 0x1FFFu) == 0u) atomicAdd(&cx, 1);
    unsigned int t = vw >> 8;
    if (t == 0u || t == 0x00FFFFFFu) atomicAdd(&cw, 1);
    if ((vs & 0x1FFFu) == 0u) atomicAdd(&cs, 1);
    __syncthreads();
    if (threadIdx.x == 0) {
        int f = 0;
        if (cx >= 120) f |= 1;
        if (cw >= 120) f |= 2;
        if (cs >= 120) f |= 4;
        g_flags = f;
    }
}

// ---------------------------------------------------------------------------
// Merged preprocessing (math proven in R12, rel_err identical):
//   blocks [0, DQ_BLOCKS): dequantize w -> g_deq, 16 outputs/thread
//   blocks [DQ_BLOCKS, +CV_BLOCKS): funnel x -> g_x fp16, 16 outputs/thread
// ---------------------------------------------------------------------------
#define DQ_BLOCKS 11008
#define CV_BLOCKS 8192
__global__ void __launch_bounds__(256) preproc_kernel(const void* __restrict__ xp,
                                                      const void* __restrict__ wp,
                                                      const void* __restrict__ sp) {
    const int flags = g_flags;
    const int bid = blockIdx.x;
    if (bid < DQ_BLOCKS) {
        int t = bid * 256 + threadIdx.x;   // 2,818,048 threads
        int i   = t >> 8;                  // row 0..11007 (256 packets/row)
        int p16 = t & 255;                 // 16-col packet
        int jg  = p16 >> 2;                // 64-col group
        int within = (p16 & 3) << 4;       // byte offset in group: 0/16/32/48

        size_t elem = (size_t)(i * 32 + (jg >> 1)) * 64 + within;

        unsigned char bytes[16];
        if (flags & 2) {   // w widened to int32
            const int4* pi = reinterpret_cast<const int4*>((const int*)wp + elem);
            int4 a = pi[0], b = pi[1], c = pi[2], d = pi[3];
            bytes[0]=(unsigned char)a.x;  bytes[1]=(unsigned char)a.y;
            bytes[2]=(unsigned char)a.z;  bytes[3]=(unsigned char)a.w;
            bytes[4]=(unsigned char)b.x;  bytes[5]=(unsigned char)b.y;
            bytes[6]=(unsigned char)b.z;  bytes[7]=(unsigned char)b.w;
            bytes[8]=(unsigned char)c.x;  bytes[9]=(unsigned char)c.y;
            bytes[10]=(unsigned char)c.z; bytes[11]=(unsigned char)c.w;
            bytes[12]=(unsigned char)d.x; bytes[13]=(unsigned char)d.y;
            bytes[14]=(unsigned char)d.z; bytes[15]=(unsigned char)d.w;
        } else {
            *reinterpret_cast<uint4*>(bytes) =
                *reinterpret_cast<const uint4*>((const signed char*)wp + elem);
        }

        float scale = (flags & 4) ? ((const float*)sp)[i * 64 + jg]
                                  : __half2float(((const __half*)sp)[i * 64 + jg]);
        bool hi = (jg & 1) == 0;

        __align__(16) __half out[16];
#pragma unroll
        for (int b = 0; b < 16; b++) {
            signed char sc = (signed char)bytes[b];
            int v;
            if (hi) v = sc >> 4;
            else    v = (sc & 15) - ((sc & 8) << 1);
            out[b] = __float2half(v * scale);
        }
        uint4* dst = reinterpret_cast<uint4*>(&g_deq[(size_t)i * K_DIM + ((size_t)p16 << 4)]);
        dst[0] = reinterpret_cast<const uint4*>(out)[0];
        dst[1] = reinterpret_cast<const uint4*>(out)[1];
    } else {
        size_t t = (size_t)(bid - DQ_BLOCKS) * 256 + threadIdx.x;  // 2,097,152
        __align__(16) __half out[16];
        if (flags & 1) {
            const float4* p = (const float4*)xp + t * 4;
            float4 f0 = p[0], f1 = p[1], f2 = p[2], f3 = p[3];
            out[0]=__float2half(f0.x);  out[1]=__float2half(f0.y);
            out[2]=__float2half(f0.z);  out[3]=__float2half(f0.w);
            out[4]=__float2half(f1.x);  out[5]=__float2half(f1.y);
            out[6]=__float2half(f1.z);  out[7]=__float2half(f1.w);
            out[8]=__float2half(f2.x);  out[9]=__float2half(f2.y);
            out[10]=__float2half(f2.z); out[11]=__float2half(f2.w);
            out[12]=__float2half(f3.x); out[13]=__float2half(f3.y);
            out[14]=__float2half(f3.z); out[15]=__float2half(f3.w);
        } else {
            const uint4* p = (const uint4*)xp + t * 2;
            reinterpret_cast<uint4*>(out)[0] = p[0];
            reinterpret_cast<uint4*>(out)[1] = p[1];
        }
        uint4* dst = reinterpret_cast<uint4*>(&g_x[t * 16]);
        dst[0] = reinterpret_cast<const uint4*>(out)[0];
        dst[1] = reinterpret_cast<const uint4*>(out)[1];
    }
}

// ---------------------------------------------------------------------------
// GEMM — byte-identical to R9's proven-best mainloop.
// grid (43, 64), cluster (1,4,1), 544 threads:
//   warps 0-15: mma.sync consumers (warp tile 32x64)
//   warp 16:    TMA producer (A per-CTA, B slice multicast)
// ---------------------------------------------------------------------------
__global__ void __launch_bounds__(NTHREADS, 1) gemm_tc(
    const __grid_constant__ CUtensorMap tmapA,
    const __grid_constant__ CUtensorMap tmapB,
    void* __restrict__ y)
{
    extern __shared__ char smem[];
    const uint32_t sb   = smem_u32(smem);
    const int tid  = threadIdx.x;
    const int lane = tid & 31;
    const int warp = tid >> 5;
    const uint32_t rank = ctarank();
    const int ntile = blockIdx.x;
    const int mtile = blockIdx.y;

    const uint32_t full0  = sb + BAR_OFF;
    const uint32_t empty0 = sb + BAR_OFF + 32;

    if (tid == 0) {
#pragma unroll
        for (int s = 0; s < STAGES; s++) {
            mbar_init(full0 + s * 8, 1);
            mbar_init(empty0 + s * 8, NWARPS_C * CLUSTER_M);
        }
    }
    __syncthreads();
    cluster_sync();

    if (warp == NWARPS_C) {
        // ---------------- TMA producer ----------------
        if (elect_one()) {
            int stage = 0, phase = 1;
            for (int kt = 0; kt < KTILES; kt++) {
                mbar_wait_relaxed(empty0 + stage * 8, phase);
                uint32_t fb = full0 + stage * 8;
                mbar_expect_tx(fb, STAGE_TX);
                tma_load(sb + SMEM_A_OFF + stage * SMEM_A_STAGE, &tmapA,
                         kt * BK, mtile * BM, fb);
                tma_load_mc(sb + SMEM_B_OFF + stage * SMEM_B_STAGE + rank * SMEM_B_SLICE,
                            &tmapB, kt * BK, ntile * BN + (int)rank * 64, fb, 0xF);
                if (++stage == STAGES) { stage = 0; phase ^= 1; }
            }
        }
    } else {
        // ---------------- consumers ----------------
        const int wm = warp & 3;    // 32 rows each
        const int wn = warp >> 2;   // 64 cols each

        float acc[2][8][4];
#pragma unroll
        for (int i = 0; i < 2; i++)
#pragma unroll
            for (int j = 0; j < 8; j++)
#pragma unroll
                for (int k = 0; k < 4; k++) acc[i][j][k] = 0.f;

        const int a_off0 = (wm * 32 + (lane & 15)) * 128 + (((lane >> 4) << 3) << 1);
        const int b_off0 = (wn * 64 + (lane & 7) + ((lane >> 4) << 3)) * 128
                         + ((((lane >> 3) & 1) << 3) << 1);

        int stage = 0, phase = 0;
        for (int kt = 0; kt < KTILES; kt++) {
            mbar_wait(full0 + stage * 8, phase);
            const uint32_t a_base = sb + SMEM_A_OFF + stage * SMEM_A_STAGE;
            const uint32_t b_base = sb + SMEM_B_OFF + stage * SMEM_B_STAGE;

#pragma unroll
            for (int ks = 0; ks < 4; ks++) {
                uint32_t a[2][4];
#pragma unroll
                for (int mi = 0; mi < 2; mi++) {
                    int byte = a_off0 + mi * 2048 + ks * 32;
                    ldsm4(a[mi][0], a[mi][1], a[mi][2], a[mi][3], a_base + SW128(byte));
                }
                uint32_t b[4][4];
#pragma unroll
                for (int ni2 = 0; ni2 < 4; ni2++) {
                    int byte = b_off0 + ni2 * 2048 + ks * 32;
                    ldsm4(b[ni2][0], b[ni2][1], b[ni2][2], b[ni2][3], b_base + SW128(byte));
                }
#pragma unroll
                for (int mi = 0; mi < 2; mi++)
#pragma unroll
                    for (int ni = 0; ni < 8; ni++)
                        mma16816(acc[mi][ni], a[mi], &b[ni >> 1][(ni & 1) * 2]);
            }

            if (elect_one()) {
#pragma unroll
                for (int r = 0; r < CLUSTER_M; r++)
                    mbar_arrive_cluster(empty0 + stage * 8, r);
            }
            if (++stage == STAGES) { stage = 0; phase ^= 1; }
        }

        // ---------------- epilogue ----------------
        const int flags = g_flags;
        const size_t base_m = (size_t)mtile * BM + wm * 32;
        const int base_n = ntile * BN + wn * 64;
#pragma unroll
        for (int mi = 0; mi < 2; mi++) {
            size_t m0 = base_m + mi * 16 + (lane >> 2);
#pragma unroll
            for (int ni = 0; ni < 8; ni++) {
                int n = base_n + ni * 8 + (lane & 3) * 2;
                __half h0 = __float2half(acc[mi][ni][0]);
                __half h1 = __float2half(acc[mi][ni][1]);
                __half h2 = __float2half(acc[mi][ni][2]);
                __half h3 = __float2half(acc[mi][ni][3]);
                if (flags & 1) {
                    float* yf = (float*)y;
                    *reinterpret_cast<float2*>(yf + m0 * N_DIM + n) =
                        make_float2(__half2float(h0), __half2float(h1));
                    *reinterpret_cast<float2*>(yf + (m0 + 8) * N_DIM + n) =
                        make_float2(__half2float(h2), __half2float(h3));
                } else {
                    __half* yh = (__half*)y;
                    *reinterpret_cast<__half2*>(yh + m0 * N_DIM + n) =
                        __halves2half2(h0, h1);
                    *reinterpret_cast<__half2*>(yh + (m0 + 8) * N_DIM + n) =
                        __halves2half2(h2, h3);
                }
            }
        }
    }

    cluster_sync();
}

// ---------------------------------------------------------------------------
// kernel_launch — inputs by element count: x=33,554,432 w=22,544,384 s=704,512
// ---------------------------------------------------------------------------
typedef CUresult (*EncodeFn)(CUtensorMap*, CUtensorMapDataType, cuuint32_t, void*,
                             const cuuint64_t*, const cuuint64_t*, const cuuint32_t*,
                             const cuuint32_t*, CUtensorMapInterleave, CUtensorMapSwizzle,
                             CUtensorMapL2promotion, CUtensorMapFloatOOBfill);

extern "C" void kernel_launch(void* const* d_in, const int* in_sizes, int n_in,
                              void* d_out, int out_size) {
    const void* x = nullptr; const void* w = nullptr; const void* s = nullptr;
    for (int i = 0; i < n_in; i++) {
        if      (in_sizes[i] == 33554432) x = d_in[i];
        else if (in_sizes[i] == 22544384) w = d_in[i];
        else if (in_sizes[i] == 704512)   s = d_in[i];
    }

    detect_kernel<<<1, 128>>>((const unsigned int*)x, (const unsigned int*)w,
                              (const unsigned int*)s);
    preproc_kernel<<<DQ_BLOCKS + CV_BLOCKS, 256>>>(x, w, s);

    static CUtensorMap tA, tB;
    static bool built = false;
    if (!built) {
        void* encode_raw = nullptr;
        cudaDriverEntryPointQueryResult qr;
        cudaGetDriverEntryPointByVersion("cuTensorMapEncodeTiled", &encode_raw, 12000,
                                         cudaEnableDefault, &qr);
        EncodeFn encode = (EncodeFn)encode_raw;
        void* pa = nullptr; void* pb = nullptr;
        cudaGetSymbolAddress(&pa, g_x);
        cudaGetSymbolAddress(&pb, g_deq);

        cuuint64_t dA[3] = {K_DIM, M_DIM, 1};
        cuuint64_t sA[2] = {K_DIM * 2ull, (cuuint64_t)K_DIM * M_DIM * 2ull};
        cuuint32_t bA[3] = {BK, BM, 1};
        cuuint32_t eS[3] = {1, 1, 1};
        encode(&tA, CU_TENSOR_MAP_DATA_TYPE_FLOAT16, 3, pa, dA, sA, bA, eS,
               CU_TENSOR_MAP_INTERLEAVE_NONE, CU_TENSOR_MAP_SWIZZLE_128B,
               CU_TENSOR_MAP_L2_PROMOTION_L2_128B, CU_TENSOR_MAP_FLOAT_OOB_FILL_NONE);

        cuuint64_t dB[3] = {K_DIM, N_DIM, 1};
        cuuint64_t sB[2] = {K_DIM * 2ull, (cuuint64_t)K_DIM * N_DIM * 2ull};
        cuuint32_t bB[3] = {BK, 64, 1};
        encode(&tB, CU_TENSOR_MAP_DATA_TYPE_FLOAT16, 3, pb, dB, sB, bB, eS,
               CU_TENSOR_MAP_INTERLEAVE_NONE, CU_TENSOR_MAP_SWIZZLE_128B,
               CU_TENSOR_MAP_L2_PROMOTION_L2_128B, CU_TENSOR_MAP_FLOAT_OOB_FILL_NONE);

        cudaFuncSetAttribute(gemm_tc, cudaFuncAttributeMaxDynamicSharedMemorySize,
                             SMEM_TOTAL);
        built = true;
    }

    cudaLaunchConfig_t cfg = {};
    cfg.gridDim  = {NTILES, MTILES, 1};
    cfg.blockDim = {NTHREADS, 1, 1};
    cfg.dynamicSmemBytes = SMEM_TOTAL;
    cfg.stream = 0;
    cudaLaunchAttribute attrs[1];
    attrs[0].id = cudaLaunchAttributeClusterDimension;
    attrs[0].val.clusterDim = {1, CLUSTER_M, 1};
    cfg.attrs = attrs;
    cfg.numAttrs = 1;
    cudaLaunchKernelEx(&cfg, gemm_tc, tA, tB, d_out);
}

// round 15
// speedup vs baseline: 1.1533x; 1.1108x over previous
#include <cuda_runtime.h>
#include <cuda.h>
#include <cuda_fp16.h>
#include <cstdint>

// ---------------------------------------------------------------------------
// Problem dims
// ---------------------------------------------------------------------------
#define M_DIM 8192
#define N_DIM 11008
#define K_DIM 4096

#define BM 128
#define BN 128                     // halved: enables 2 CTAs/SM
#define BK 64                      // 64 fp16 = 128B row = SW128 atom
#define STAGES 3
#define KTILES (K_DIM / BK)        // 64
#define CLUSTER_M 4
#define NTILES (N_DIM / BN)        // 86
#define MTILES (M_DIM / BM)        // 64

#define NWARPS_C 8                 // consumer warps
#define NTHREADS (NWARPS_C * 32 + 32)   // 288

// SMEM layout (per CTA: 96.1 KB -> 2 CTAs/SM)
#define SMEM_A_STAGE 16384         // 128 rows x 128B
#define SMEM_B_STAGE 16384         // 128 rows x 128B
#define SMEM_B_SLICE 4096          // 32 rows x 128B
#define SMEM_A_OFF 0
#define SMEM_B_OFF (STAGES * SMEM_A_STAGE)               // 49152
#define BAR_OFF (SMEM_B_OFF + STAGES * SMEM_B_STAGE)     // 98304
#define SMEM_TOTAL (BAR_OFF + 128)                       // 98432
#define STAGE_TX (SMEM_A_STAGE + SMEM_B_STAGE)           // 32768

// Device-global scratch
__device__ __half g_x[(size_t)M_DIM * K_DIM];
__device__ __half g_deq[(size_t)N_DIM * K_DIM];
__device__ int    g_flags;   // bit0: x/out fp32, bit1: w int32, bit2: s fp32

// ---------------------------------------------------------------------------
// PTX helpers
// ---------------------------------------------------------------------------
__device__ __forceinline__ uint32_t smem_u32(const void* p) {
    return (uint32_t)__cvta_generic_to_shared(p);
}
__device__ __forceinline__ uint32_t elect_one() {
    uint32_t pred;
    asm volatile("{\n\t.reg .pred p;\n\telect.sync _|p, 0xFFFFFFFF;\n\t"
                 "selp.b32 %0, 1, 0, p;\n\t}" : "=r"(pred));
    return pred;
}
__device__ __forceinline__ uint32_t ctarank() {
    uint32_t r; asm("mov.u32 %0, %%cluster_ctarank;" : "=r"(r)); return r;
}
__device__ __forceinline__ void mbar_init(uint32_t a, uint32_t n) {
    asm volatile("mbarrier.init.shared.b64 [%0], %1;" :: "r"(a), "r"(n) : "memory");
}
__device__ __forceinline__ void mbar_expect_tx(uint32_t a, uint32_t b) {
    asm volatile("mbarrier.arrive.expect_tx.shared.b64 _, [%0], %1;" :: "r"(a), "r"(b) : "memory");
}
__device__ __forceinline__ void mbar_wait(uint32_t a, uint32_t parity) {
    asm volatile("{\n\t.reg .pred P;\n\t"
                 "W_%=:\n\t"
                 "mbarrier.try_wait.parity.acquire.cta.shared::cta.b64 P, [%0], %1, 0x989680;\n\t"
                 "@P bra.uni D_%=;\n\t"
                 "bra.uni W_%=;\n\t"
                 "D_%=:\n\t}" :: "r"(a), "r"(parity) : "memory");
}
__device__ __forceinline__ void mbar_wait_relaxed(uint32_t a, uint32_t parity) {
    asm volatile("{\n\t.reg .pred P;\n\t"
                 "W_%=:\n\t"
                 "mbarrier.try_wait.parity.relaxed.cta.shared::cta.b64 P, [%0], %1, 0x989680;\n\t"
                 "@P bra.uni D_%=;\n\t"
                 "bra.uni W_%=;\n\t"
                 "D_%=:\n\t}" :: "r"(a), "r"(parity) : "memory");
}
__device__ __forceinline__ void mbar_arrive_cluster(uint32_t local_addr, uint32_t rank) {
    asm volatile("{\n\t.reg .b32 ra;\n\t"
                 "mapa.shared::cluster.u32 ra, %0, %1;\n\t"
                 "mbarrier.arrive.shared::cluster.b64 _, [ra];\n\t}"
                 :: "r"(local_addr), "r"(rank) : "memory");
}
__device__ __forceinline__ void tma_load(uint32_t dst, const void* map, int x, int y,
                                         uint32_t mbar) {
    asm volatile("cp.async.bulk.tensor.3d.shared::cta.global.tile.mbarrier::complete_tx::bytes "
                 "[%0], [%1, {%2, %3, %4}], [%5];"
                 :: "r"(dst), "l"(map), "r"(x), "r"(y), "r"(0), "r"(mbar) : "memory");
}
__device__ __forceinline__ void tma_load_mc(uint32_t dst, const void* map, int x, int y,
                                            uint32_t mbar, uint16_t mask) {
    asm volatile("cp.async.bulk.tensor.3d.shared::cluster.global.tile."
                 "mbarrier::complete_tx::bytes.multicast::cluster "
                 "[%0], [%1, {%2, %3, %4}], [%5], %6;"
                 :: "r"(dst), "l"(map), "r"(x), "r"(y), "r"(0), "r"(mbar), "h"(mask) : "memory");
}
__device__ __forceinline__ void cluster_sync() {
    asm volatile("barrier.cluster.arrive.aligned;" ::: "memory");
    asm volatile("barrier.cluster.wait.aligned;" ::: "memory");
}
__device__ __forceinline__ void ldsm4(uint32_t& r0, uint32_t& r1,
                                      uint32_t& r2, uint32_t& r3, uint32_t sa) {
    asm volatile("ldmatrix.sync.aligned.m8n8.x4.shared.b16 {%0,%1,%2,%3}, [%4];\n"
                 : "=r"(r0), "=r"(r1), "=r"(r2), "=r"(r3) : "r"(sa));
}
__device__ __forceinline__ void mma16816(float* c, const uint32_t* a, const uint32_t* b) {
    asm volatile("mma.sync.aligned.m16n8k16.row.col.f32.f16.f16.f32 "
                 "{%0,%1,%2,%3}, {%4,%5,%6,%7}, {%8,%9}, {%0,%1,%2,%3};\n"
                 : "+f"(c[0]), "+f"(c[1]), "+f"(c[2]), "+f"(c[3])
                 : "r"(a[0]), "r"(a[1]), "r"(a[2]), "r"(a[3]),
                   "r"(b[0]), "r"(b[1]));
}
#define SW128(b) ((b) ^ (((b) >> 3) & 0x70))

// ---------------------------------------------------------------------------
// Dtype detection (proven)
// ---------------------------------------------------------------------------
__global__ void detect_kernel(const unsigned int* __restrict__ xw,
                              const unsigned int* __restrict__ ww,
                              const unsigned int* __restrict__ sw) {
    __shared__ int cx, cw, cs;
    if (threadIdx.x == 0) { cx = 0; cw = 0; cs = 0; }
    __syncthreads();
    unsigned int vx = xw[threadIdx.x];
    unsigned int vw = ww[threadIdx.x];
    unsigned int vs = sw[threadIdx.x];
    if ((vx & 0x1FFFu) == 0u) atomicAdd(&cx, 1);
    unsigned int t = vw >> 8;
    if (t == 0u || t == 0x00FFFFFFu) atomicAdd(&cw, 1);
    if ((vs & 0x1FFFu) == 0u) atomicAdd(&cs, 1);
    __syncthreads();
    if (threadIdx.x == 0) {
        int f = 0;
        if (cx >= 120) f |= 1;
        if (cw >= 120) f |= 2;
        if (cs >= 120) f |= 4;
        g_flags = f;
    }
}

// ---------------------------------------------------------------------------
// Merged preprocessing (proven in R14)
// ---------------------------------------------------------------------------
#define DQ_BLOCKS 11008
#define CV_BLOCKS 8192
__global__ void __launch_bounds__(256) preproc_kernel(const void* __restrict__ xp,
                                                      const void* __restrict__ wp,
                                                      const void* __restrict__ sp) {
    const int flags = g_flags;
    const int bid = blockIdx.x;
    if (bid < DQ_BLOCKS) {
        int t = bid * 256 + threadIdx.x;
        int i   = t >> 8;
        int p16 = t & 255;
        int jg  = p16 >> 2;
        int within = (p16 & 3) << 4;

        size_t elem = (size_t)(i * 32 + (jg >> 1)) * 64 + within;

        unsigned char bytes[16];
        if (flags & 2) {
            const int4* pi = reinterpret_cast<const int4*>((const int*)wp + elem);
            int4 a = pi[0], b = pi[1], c = pi[2], d = pi[3];
            bytes[0]=(unsigned char)a.x;  bytes[1]=(unsigned char)a.y;
            bytes[2]=(unsigned char)a.z;  bytes[3]=(unsigned char)a.w;
            bytes[4]=(unsigned char)b.x;  bytes[5]=(unsigned char)b.y;
            bytes[6]=(unsigned char)b.z;  bytes[7]=(unsigned char)b.w;
            bytes[8]=(unsigned char)c.x;  bytes[9]=(unsigned char)c.y;
            bytes[10]=(unsigned char)c.z; bytes[11]=(unsigned char)c.w;
            bytes[12]=(unsigned char)d.x; bytes[13]=(unsigned char)d.y;
            bytes[14]=(unsigned char)d.z; bytes[15]=(unsigned char)d.w;
        } else {
            *reinterpret_cast<uint4*>(bytes) =
                *reinterpret_cast<const uint4*>((const signed char*)wp + elem);
        }

        float scale = (flags & 4) ? ((const float*)sp)[i * 64 + jg]
                                  : __half2float(((const __half*)sp)[i * 64 + jg]);
        bool hi = (jg & 1) == 0;

        __align__(16) __half out[16];
#pragma unroll
        for (int b = 0; b < 16; b++) {
            signed char sc = (signed char)bytes[b];
            int v;
            if (hi) v = sc >> 4;
            else    v = (sc & 15) - ((sc & 8) << 1);
            out[b] = __float2half(v * scale);
        }
        uint4* dst = reinterpret_cast<uint4*>(&g_deq[(size_t)i * K_DIM + ((size_t)p16 << 4)]);
        dst[0] = reinterpret_cast<const uint4*>(out)[0];
        dst[1] = reinterpret_cast<const uint4*>(out)[1];
    } else {
        size_t t = (size_t)(bid - DQ_BLOCKS) * 256 + threadIdx.x;
        __align__(16) __half out[16];
        if (flags & 1) {
            const float4* p = (const float4*)xp + t * 4;
            float4 f0 = p[0], f1 = p[1], f2 = p[2], f3 = p[3];
            out[0]=__float2half(f0.x);  out[1]=__float2half(f0.y);
            out[2]=__float2half(f0.z);  out[3]=__float2half(f0.w);
            out[4]=__float2half(f1.x);  out[5]=__float2half(f1.y);
            out[6]=__float2half(f1.z);  out[7]=__float2half(f1.w);
            out[8]=__float2half(f2.x);  out[9]=__float2half(f2.y);
            out[10]=__float2half(f2.z); out[11]=__float2half(f2.w);
            out[12]=__float2half(f3.x); out[13]=__float2half(f3.y);
            out[14]=__float2half(f3.z); out[15]=__float2half(f3.w);
        } else {
            const uint4* p = (const uint4*)xp + t * 2;
            reinterpret_cast<uint4*>(out)[0] = p[0];
            reinterpret_cast<uint4*>(out)[1] = p[1];
        }
        uint4* dst = reinterpret_cast<uint4*>(&g_x[t * 16]);
        dst[0] = reinterpret_cast<const uint4*>(out)[0];
        dst[1] = reinterpret_cast<const uint4*>(out)[1];
    }
}

// ---------------------------------------------------------------------------
// GEMM: grid (86, 64), cluster (1,4,1), 288 threads, 2 CTAs/SM.
//   warps 0-7: mma.sync consumers (warp tile 32x64; wm 0..3, wn 0..1)
//   warp 8:    TMA producer (A per-CTA, B 32-row slice multicast)
// Mainloop body identical to the proven R9/R14 inner loop.
// ---------------------------------------------------------------------------
__global__ void __launch_bounds__(NTHREADS, 2) gemm_tc(
    const __grid_constant__ CUtensorMap tmapA,
    const __grid_constant__ CUtensorMap tmapB,
    void* __restrict__ y)
{
    extern __shared__ char smem[];
    const uint32_t sb   = smem_u32(smem);
    const int tid  = threadIdx.x;
    const int lane = tid & 31;
    const int warp = tid >> 5;
    const uint32_t rank = ctarank();
    const int ntile = blockIdx.x;
    const int mtile = blockIdx.y;

    const uint32_t full0  = sb + BAR_OFF;        // full[s]  = full0 + 8s
    const uint32_t empty0 = sb + BAR_OFF + 32;   // empty[s] = empty0 + 8s

    if (tid == 0) {
#pragma unroll
        for (int s = 0; s < STAGES; s++) {
            mbar_init(full0 + s * 8, 1);
            mbar_init(empty0 + s * 8, NWARPS_C * CLUSTER_M);   // 32 warp releases
        }
    }
    __syncthreads();
    cluster_sync();

    if (warp == NWARPS_C) {
        // ---------------- TMA producer ----------------
        if (elect_one()) {
            int stage = 0, phase = 1;
            for (int kt = 0; kt < KTILES; kt++) {
                mbar_wait_relaxed(empty0 + stage * 8, phase);
                uint32_t fb = full0 + stage * 8;
                mbar_expect_tx(fb, STAGE_TX);
                tma_load(sb + SMEM_A_OFF + stage * SMEM_A_STAGE, &tmapA,
                         kt * BK, mtile * BM, fb);
                tma_load_mc(sb + SMEM_B_OFF + stage * SMEM_B_STAGE + rank * SMEM_B_SLICE,
                            &tmapB, kt * BK, ntile * BN + (int)rank * 32, fb, 0xF);
                if (++stage == STAGES) { stage = 0; phase ^= 1; }
            }
        }
    } else {
        // ---------------- consumers ----------------
        const int wm = warp & 3;    // 0..3 -> 32 rows each
        const int wn = warp >> 2;   // 0..1 -> 64 cols each

        float acc[2][8][4];
#pragma unroll
        for (int i = 0; i < 2; i++)
#pragma unroll
            for (int j = 0; j < 8; j++)
#pragma unroll
                for (int k = 0; k < 4; k++) acc[i][j][k] = 0.f;

        const int a_off0 = (wm * 32 + (lane & 15)) * 128 + (((lane >> 4) << 3) << 1);
        const int b_off0 = (wn * 64 + (lane & 7) + ((lane >> 4) << 3)) * 128
                         + ((((lane >> 3) & 1) << 3) << 1);

        int stage = 0, phase = 0;
        for (int kt = 0; kt < KTILES; kt++) {
            mbar_wait(full0 + stage * 8, phase);
            const uint32_t a_base = sb + SMEM_A_OFF + stage * SMEM_A_STAGE;
            const uint32_t b_base = sb + SMEM_B_OFF + stage * SMEM_B_STAGE;

#pragma unroll
            for (int ks = 0; ks < 4; ks++) {
                uint32_t a[2][4];
#pragma unroll
                for (int mi = 0; mi < 2; mi++) {
                    int byte = a_off0 + mi * 2048 + ks * 32;
                    ldsm4(a[mi][0], a[mi][1], a[mi][2], a[mi][3], a_base + SW128(byte));
                }
                uint32_t b[4][4];
#pragma unroll
                for (int ni2 = 0; ni2 < 4; ni2++) {
                    int byte = b_off0 + ni2 * 2048 + ks * 32;
                    ldsm4(b[ni2][0], b[ni2][1], b[ni2][2], b[ni2][3], b_base + SW128(byte));
                }
#pragma unroll
                for (int mi = 0; mi < 2; mi++)
#pragma unroll
                    for (int ni = 0; ni < 8; ni++)
                        mma16816(acc[mi][ni], a[mi], &b[ni >> 1][(ni & 1) * 2]);
            }

            if (elect_one()) {
#pragma unroll
                for (int r = 0; r < CLUSTER_M; r++)
                    mbar_arrive_cluster(empty0 + stage * 8, r);
            }
            if (++stage == STAGES) { stage = 0; phase ^= 1; }
        }

        // ---------------- epilogue ----------------
        const int flags = g_flags;
        const size_t base_m = (size_t)mtile * BM + wm * 32;
        const int base_n = ntile * BN + wn * 64;
#pragma unroll
        for (int mi = 0; mi < 2; mi++) {
            size_t m0 = base_m + mi * 16 + (lane >> 2);
#pragma unroll
            for (int ni = 0; ni < 8; ni++) {
                int n = base_n + ni * 8 + (lane & 3) * 2;
                __half h0 = __float2half(acc[mi][ni][0]);
                __half h1 = __float2half(acc[mi][ni][1]);
                __half h2 = __float2half(acc[mi][ni][2]);
                __half h3 = __float2half(acc[mi][ni][3]);
                if (flags & 1) {
                    float* yf = (float*)y;
                    *reinterpret_cast<float2*>(yf + m0 * N_DIM + n) =
                        make_float2(__half2float(h0), __half2float(h1));
                    *reinterpret_cast<float2*>(yf + (m0 + 8) * N_DIM + n) =
                        make_float2(__half2float(h2), __half2float(h3));
                } else {
                    __half* yh = (__half*)y;
                    *reinterpret_cast<__half2*>(yh + m0 * N_DIM + n) =
                        __halves2half2(h0, h1);
                    *reinterpret_cast<__half2*>(yh + (m0 + 8) * N_DIM + n) =
                        __halves2half2(h2, h3);
                }
            }
        }
    }

    cluster_sync();
}

// ---------------------------------------------------------------------------
// kernel_launch — inputs by element count: x=33,554,432 w=22,544,384 s=704,512
// ---------------------------------------------------------------------------
typedef CUresult (*EncodeFn)(CUtensorMap*, CUtensorMapDataType, cuuint32_t, void*,
                             const cuuint64_t*, const cuuint64_t*, const cuuint32_t*,
                             const cuuint32_t*, CUtensorMapInterleave, CUtensorMapSwizzle,
                             CUtensorMapL2promotion, CUtensorMapFloatOOBfill);

extern "C" void kernel_launch(void* const* d_in, const int* in_sizes, int n_in,
                              void* d_out, int out_size) {
    const void* x = nullptr; const void* w = nullptr; const void* s = nullptr;
    for (int i = 0; i < n_in; i++) {
        if      (in_sizes[i] == 33554432) x = d_in[i];
        else if (in_sizes[i] == 22544384) w = d_in[i];
        else if (in_sizes[i] == 704512)   s = d_in[i];
    }

    detect_kernel<<<1, 128>>>((const unsigned int*)x, (const unsigned int*)w,
                              (const unsigned int*)s);
    preproc_kernel<<<DQ_BLOCKS + CV_BLOCKS, 256>>>(x, w, s);

    static CUtensorMap tA, tB;
    static bool built = false;
    if (!built) {
        void* encode_raw = nullptr;
        cudaDriverEntryPointQueryResult qr;
        cudaGetDriverEntryPointByVersion("cuTensorMapEncodeTiled", &encode_raw, 12000,
                                         cudaEnableDefault, &qr);
        EncodeFn encode = (EncodeFn)encode_raw;
        void* pa = nullptr; void* pb = nullptr;
        cudaGetSymbolAddress(&pa, g_x);
        cudaGetSymbolAddress(&pb, g_deq);

        cuuint64_t dA[3] = {K_DIM, M_DIM, 1};
        cuuint64_t sA[2] = {K_DIM * 2ull, (cuuint64_t)K_DIM * M_DIM * 2ull};
        cuuint32_t bA[3] = {BK, BM, 1};
        cuuint32_t eS[3] = {1, 1, 1};
        encode(&tA, CU_TENSOR_MAP_DATA_TYPE_FLOAT16, 3, pa, dA, sA, bA, eS,
               CU_TENSOR_MAP_INTERLEAVE_NONE, CU_TENSOR_MAP_SWIZZLE_128B,
               CU_TENSOR_MAP_L2_PROMOTION_L2_128B, CU_TENSOR_MAP_FLOAT_OOB_FILL_NONE);

        cuuint64_t dB[3] = {K_DIM, N_DIM, 1};
        cuuint64_t sB[2] = {K_DIM * 2ull, (cuuint64_t)K_DIM * N_DIM * 2ull};
        cuuint32_t bB[3] = {BK, 32, 1};   // one cooperative slice (32 N-rows)
        encode(&tB, CU_TENSOR_MAP_DATA_TYPE_FLOAT16, 3, pb, dB, sB, bB, eS,
               CU_TENSOR_MAP_INTERLEAVE_NONE, CU_TENSOR_MAP_SWIZZLE_128B,
               CU_TENSOR_MAP_L2_PROMOTION_L2_128B, CU_TENSOR_MAP_FLOAT_OOB_FILL_NONE);

        cudaFuncSetAttribute(gemm_tc, cudaFuncAttributeMaxDynamicSharedMemorySize,
                             SMEM_TOTAL);
        built = true;
    }

    cudaLaunchConfig_t cfg = {};
    cfg.gridDim  = {NTILES, MTILES, 1};   // (86, 64)
    cfg.blockDim = {NTHREADS, 1, 1};
    cfg.dynamicSmemBytes = SMEM_TOTAL;
    cfg.stream = 0;
    cudaLaunchAttribute attrs[1];
    attrs[0].id = cudaLaunchAttributeClusterDimension;
    attrs[0].val.clusterDim = {1, CLUSTER_M, 1};
    cfg.attrs = attrs;
    cfg.numAttrs = 1;
    cudaLaunchKernelEx(&cfg, gemm_tc, tA, tB, d_out);
}

// round 16
// speedup vs baseline: 1.1882x; 1.0303x over previous
#include <cuda_runtime.h>
#include <cuda.h>
#include <cuda_fp16.h>
#include <cstdint>

// ---------------------------------------------------------------------------
// Problem dims
// ---------------------------------------------------------------------------
#define M_DIM 8192
#define N_DIM 11008
#define K_DIM 4096

#define BM 128
#define BN 128
#define BK 64                      // 64 fp16 = 128B row = SW128 atom
#define STAGES 3
#define KTILES (K_DIM / BK)        // 64
#define CLUSTER_M 2                // cluster 2 packs 148 SMs perfectly (74 pairs)
#define NTILES (N_DIM / BN)        // 86
#define MTILES (M_DIM / BM)        // 64

#define NWARPS_C 8                 // consumer warps
#define NTHREADS (NWARPS_C * 32 + 32)   // 288

// SMEM layout (per CTA: 96.1 KB -> 2 CTAs/SM)
#define SMEM_A_STAGE 16384         // 128 rows x 128B
#define SMEM_B_STAGE 16384         // 128 rows x 128B
#define SMEM_B_SLICE 8192          // 64 rows x 128B (one cooperative slice)
#define SMEM_A_OFF 0
#define SMEM_B_OFF (STAGES * SMEM_A_STAGE)               // 49152
#define BAR_OFF (SMEM_B_OFF + STAGES * SMEM_B_STAGE)     // 98304
#define SMEM_TOTAL (BAR_OFF + 128)                       // 98432
#define STAGE_TX (SMEM_A_STAGE + SMEM_B_STAGE)           // 32768

#define MCAST_MASK ((uint16_t)((1u << CLUSTER_M) - 1u))  // 0x3

// Device-global scratch
__device__ __half g_x[(size_t)M_DIM * K_DIM];
__device__ __half g_deq[(size_t)N_DIM * K_DIM];
__device__ int    g_flags;   // bit0: x/out fp32, bit1: w int32, bit2: s fp32

// ---------------------------------------------------------------------------
// PTX helpers
// ---------------------------------------------------------------------------
__device__ __forceinline__ uint32_t smem_u32(const void* p) {
    return (uint32_t)__cvta_generic_to_shared(p);
}
__device__ __forceinline__ uint32_t elect_one() {
    uint32_t pred;
    asm volatile("{\n\t.reg .pred p;\n\telect.sync _|p, 0xFFFFFFFF;\n\t"
                 "selp.b32 %0, 1, 0, p;\n\t}" : "=r"(pred));
    return pred;
}
__device__ __forceinline__ uint32_t ctarank() {
    uint32_t r; asm("mov.u32 %0, %%cluster_ctarank;" : "=r"(r)); return r;
}
__device__ __forceinline__ void mbar_init(uint32_t a, uint32_t n) {
    asm volatile("mbarrier.init.shared.b64 [%0], %1;" :: "r"(a), "r"(n) : "memory");
}
__device__ __forceinline__ void mbar_expect_tx(uint32_t a, uint32_t b) {
    asm volatile("mbarrier.arrive.expect_tx.shared.b64 _, [%0], %1;" :: "r"(a), "r"(b) : "memory");
}
__device__ __forceinline__ void mbar_wait(uint32_t a, uint32_t parity) {
    asm volatile("{\n\t.reg .pred P;\n\t"
                 "W_%=:\n\t"
                 "mbarrier.try_wait.parity.acquire.cta.shared::cta.b64 P, [%0], %1, 0x989680;\n\t"
                 "@P bra.uni D_%=;\n\t"
                 "bra.uni W_%=;\n\t"
                 "D_%=:\n\t}" :: "r"(a), "r"(parity) : "memory");
}
__device__ __forceinline__ void mbar_wait_relaxed(uint32_t a, uint32_t parity) {
    asm volatile("{\n\t.reg .pred P;\n\t"
                 "W_%=:\n\t"
                 "mbarrier.try_wait.parity.relaxed.cta.shared::cta.b64 P, [%0], %1, 0x989680;\n\t"
                 "@P bra.uni D_%=;\n\t"
                 "bra.uni W_%=;\n\t"
                 "D_%=:\n\t}" :: "r"(a), "r"(parity) : "memory");
}
__device__ __forceinline__ void mbar_arrive_cluster(uint32_t local_addr, uint32_t rank) {
    asm volatile("{\n\t.reg .b32 ra;\n\t"
                 "mapa.shared::cluster.u32 ra, %0, %1;\n\t"
                 "mbarrier.arrive.shared::cluster.b64 _, [ra];\n\t}"
                 :: "r"(local_addr), "r"(rank) : "memory");
}
__device__ __forceinline__ void tma_load(uint32_t dst, const void* map, int x, int y,
                                         uint32_t mbar) {
    asm volatile("cp.async.bulk.tensor.3d.shared::cta.global.tile.mbarrier::complete_tx::bytes "
                 "[%0], [%1, {%2, %3, %4}], [%5];"
                 :: "r"(dst), "l"(map), "r"(x), "r"(y), "r"(0), "r"(mbar) : "memory");
}
__device__ __forceinline__ void tma_load_mc(uint32_t dst, const void* map, int x, int y,
                                            uint32_t mbar, uint16_t mask) {
    asm volatile("cp.async.bulk.tensor.3d.shared::cluster.global.tile."
                 "mbarrier::complete_tx::bytes.multicast::cluster "
                 "[%0], [%1, {%2, %3, %4}], [%5], %6;"
                 :: "r"(dst), "l"(map), "r"(x), "r"(y), "r"(0), "r"(mbar), "h"(mask) : "memory");
}
__device__ __forceinline__ void cluster_sync() {
    asm volatile("barrier.cluster.arrive.aligned;" ::: "memory");
    asm volatile("barrier.cluster.wait.aligned;" ::: "memory");
}
__device__ __forceinline__ void ldsm4(uint32_t& r0, uint32_t& r1,
                                      uint32_t& r2, uint32_t& r3, uint32_t sa) {
    asm volatile("ldmatrix.sync.aligned.m8n8.x4.shared.b16 {%0,%1,%2,%3}, [%4];\n"
                 : "=r"(r0), "=r"(r1), "=r"(r2), "=r"(r3) : "r"(sa));
}
__device__ __forceinline__ void mma16816(float* c, const uint32_t* a, const uint32_t* b) {
    asm volatile("mma.sync.aligned.m16n8k16.row.col.f32.f16.f16.f32 "
                 "{%0,%1,%2,%3}, {%4,%5,%6,%7}, {%8,%9}, {%0,%1,%2,%3};\n"
                 : "+f"(c[0]), "+f"(c[1]), "+f"(c[2]), "+f"(c[3])
                 : "r"(a[0]), "r"(a[1]), "r"(a[2]), "r"(a[3]),
                   "r"(b[0]), "r"(b[1]));
}
#define SW128(b) ((b) ^ (((b) >> 3) & 0x70))

// ---------------------------------------------------------------------------
// Dtype detection (proven)
// ---------------------------------------------------------------------------
__global__ void detect_kernel(const unsigned int* __restrict__ xw,
                              const unsigned int* __restrict__ ww,
                              const unsigned int* __restrict__ sw) {
    __shared__ int cx, cw, cs;
    if (threadIdx.x == 0) { cx = 0; cw = 0; cs = 0; }
    __syncthreads();
    unsigned int vx = xw[threadIdx.x];
    unsigned int vw = ww[threadIdx.x];
    unsigned int vs = sw[threadIdx.x];
    if ((vx & 0x1FFFu) == 0u) atomicAdd(&cx, 1);
    unsigned int t = vw >> 8;
    if (t == 0u || t == 0x00FFFFFFu) atomicAdd(&cw, 1);
    if ((vs & 0x1FFFu) == 0u) atomicAdd(&cs, 1);
    __syncthreads();
    if (threadIdx.x == 0) {
        int f = 0;
        if (cx >= 120) f |= 1;
        if (cw >= 120) f |= 2;
        if (cs >= 120) f |= 4;
        g_flags = f;
    }
}

// ---------------------------------------------------------------------------
// Merged preprocessing (proven in R14/R15)
// ---------------------------------------------------------------------------
#define DQ_BLOCKS 11008
#define CV_BLOCKS 8192
__global__ void __launch_bounds__(256) preproc_kernel(const void* __restrict__ xp,
                                                      const void* __restrict__ wp,
                                                      const void* __restrict__ sp) {
    const int flags = g_flags;
    const int bid = blockIdx.x;
    if (bid < DQ_BLOCKS) {
        int t = bid * 256 + threadIdx.x;
        int i   = t >> 8;
        int p16 = t & 255;
        int jg  = p16 >> 2;
        int within = (p16 & 3) << 4;

        size_t elem = (size_t)(i * 32 + (jg >> 1)) * 64 + within;

        unsigned char bytes[16];
        if (flags & 2) {
            const int4* pi = reinterpret_cast<const int4*>((const int*)wp + elem);
            int4 a = pi[0], b = pi[1], c = pi[2], d = pi[3];
            bytes[0]=(unsigned char)a.x;  bytes[1]=(unsigned char)a.y;
            bytes[2]=(unsigned char)a.z;  bytes[3]=(unsigned char)a.w;
            bytes[4]=(unsigned char)b.x;  bytes[5]=(unsigned char)b.y;
            bytes[6]=(unsigned char)b.z;  bytes[7]=(unsigned char)b.w;
            bytes[8]=(unsigned char)c.x;  bytes[9]=(unsigned char)c.y;
            bytes[10]=(unsigned char)c.z; bytes[11]=(unsigned char)c.w;
            bytes[12]=(unsigned char)d.x; bytes[13]=(unsigned char)d.y;
            bytes[14]=(unsigned char)d.z; bytes[15]=(unsigned char)d.w;
        } else {
            *reinterpret_cast<uint4*>(bytes) =
                *reinterpret_cast<const uint4*>((const signed char*)wp + elem);
        }

        float scale = (flags & 4) ? ((const float*)sp)[i * 64 + jg]
                                  : __half2float(((const __half*)sp)[i * 64 + jg]);
        bool hi = (jg & 1) == 0;

        __align__(16) __half out[16];
#pragma unroll
        for (int b = 0; b < 16; b++) {
            signed char sc = (signed char)bytes[b];
            int v;
            if (hi) v = sc >> 4;
            else    v = (sc & 15) - ((sc & 8) << 1);
            out[b] = __float2half(v * scale);
        }
        uint4* dst = reinterpret_cast<uint4*>(&g_deq[(size_t)i * K_DIM + ((size_t)p16 << 4)]);
        dst[0] = reinterpret_cast<const uint4*>(out)[0];
        dst[1] = reinterpret_cast<const uint4*>(out)[1];
    } else {
        size_t t = (size_t)(bid - DQ_BLOCKS) * 256 + threadIdx.x;
        __align__(16) __half out[16];
        if (flags & 1) {
            const float4* p = (const float4*)xp + t * 4;
            float4 f0 = p[0], f1 = p[1], f2 = p[2], f3 = p[3];
            out[0]=__float2half(f0.x);  out[1]=__float2half(f0.y);
            out[2]=__float2half(f0.z);  out[3]=__float2half(f0.w);
            out[4]=__float2half(f1.x);  out[5]=__float2half(f1.y);
            out[6]=__float2half(f1.z);  out[7]=__float2half(f1.w);
            out[8]=__float2half(f2.x);  out[9]=__float2half(f2.y);
            out[10]=__float2half(f2.z); out[11]=__float2half(f2.w);
            out[12]=__float2half(f3.x); out[13]=__float2half(f3.y);
            out[14]=__float2half(f3.z); out[15]=__float2half(f3.w);
        } else {
            const uint4* p = (const uint4*)xp + t * 2;
            reinterpret_cast<uint4*>(out)[0] = p[0];
            reinterpret_cast<uint4*>(out)[1] = p[1];
        }
        uint4* dst = reinterpret_cast<uint4*>(&g_x[t * 16]);
        dst[0] = reinterpret_cast<const uint4*>(out)[0];
        dst[1] = reinterpret_cast<const uint4*>(out)[1];
    }
}

// ---------------------------------------------------------------------------
// GEMM: grid (86, 64), cluster (1,2,1), 288 threads, 2 CTAs/SM.
//   warps 0-7: mma.sync consumers (warp tile 32x64)
//   warp 8:    TMA producer (A per-CTA, B 64-row slice multicast to pair)
// Mainloop body identical to the proven R15 inner loop.
// ---------------------------------------------------------------------------
__global__ void __launch_bounds__(NTHREADS, 2) gemm_tc(
    const __grid_constant__ CUtensorMap tmapA,
    const __grid_constant__ CUtensorMap tmapB,
    void* __restrict__ y)
{
    extern __shared__ char smem[];
    const uint32_t sb   = smem_u32(smem);
    const int tid  = threadIdx.x;
    const int lane = tid & 31;
    const int warp = tid >> 5;
    const uint32_t rank = ctarank();
    const int ntile = blockIdx.x;
    const int mtile = blockIdx.y;

    const uint32_t full0  = sb + BAR_OFF;        // full[s]  = full0 + 8s
    const uint32_t empty0 = sb + BAR_OFF + 32;   // empty[s] = empty0 + 8s

    if (tid == 0) {
#pragma unroll
        for (int s = 0; s < STAGES; s++) {
            mbar_init(full0 + s * 8, 1);
            mbar_init(empty0 + s * 8, NWARPS_C * CLUSTER_M);   // 16 warp releases
        }
    }
    __syncthreads();
    cluster_sync();

    if (warp == NWARPS_C) {
        // ---------------- TMA producer ----------------
        if (elect_one()) {
            int stage = 0, phase = 1;
            for (int kt = 0; kt < KTILES; kt++) {
                mbar_wait_relaxed(empty0 + stage * 8, phase);
                uint32_t fb = full0 + stage * 8;
                mbar_expect_tx(fb, STAGE_TX);
                tma_load(sb + SMEM_A_OFF + stage * SMEM_A_STAGE, &tmapA,
                         kt * BK, mtile * BM, fb);
                tma_load_mc(sb + SMEM_B_OFF + stage * SMEM_B_STAGE + rank * SMEM_B_SLICE,
                            &tmapB, kt * BK, ntile * BN + (int)rank * 64, fb, MCAST_MASK);
                if (++stage == STAGES) { stage = 0; phase ^= 1; }
            }
        }
    } else {
        // ---------------- consumers ----------------
        const int wm = warp & 3;    // 0..3 -> 32 rows each
        const int wn = warp >> 2;   // 0..1 -> 64 cols each

        float acc[2][8][4];
#pragma unroll
        for (int i = 0; i < 2; i++)
#pragma unroll
            for (int j = 0; j < 8; j++)
#pragma unroll
                for (int k = 0; k < 4; k++) acc[i][j][k] = 0.f;

        const int a_off0 = (wm * 32 + (lane & 15)) * 128 + (((lane >> 4) << 3) << 1);
        const int b_off0 = (wn * 64 + (lane & 7) + ((lane >> 4) << 3)) * 128
                         + ((((lane >> 3) & 1) << 3) << 1);

        int stage = 0, phase = 0;
        for (int kt = 0; kt < KTILES; kt++) {
            mbar_wait(full0 + stage * 8, phase);
            const uint32_t a_base = sb + SMEM_A_OFF + stage * SMEM_A_STAGE;
            const uint32_t b_base = sb + SMEM_B_OFF + stage * SMEM_B_STAGE;

#pragma unroll
            for (int ks = 0; ks < 4; ks++) {
                uint32_t a[2][4];
#pragma unroll
                for (int mi = 0; mi < 2; mi++) {
                    int byte = a_off0 + mi * 2048 + ks * 32;
                    ldsm4(a[mi][0], a[mi][1], a[mi][2], a[mi][3], a_base + SW128(byte));
                }
                uint32_t b[4][4];
#pragma unroll
                for (int ni2 = 0; ni2 < 4; ni2++) {
                    int byte = b_off0 + ni2 * 2048 + ks * 32;
                    ldsm4(b[ni2][0], b[ni2][1], b[ni2][2], b[ni2][3], b_base + SW128(byte));
                }
#pragma unroll
                for (int mi = 0; mi < 2; mi++)
#pragma unroll
                    for (int ni = 0; ni < 8; ni++)
                        mma16816(acc[mi][ni], a[mi], &b[ni >> 1][(ni & 1) * 2]);
            }

            if (elect_one()) {
#pragma unroll
                for (int r = 0; r < CLUSTER_M; r++)
                    mbar_arrive_cluster(empty0 + stage * 8, r);
            }
            if (++stage == STAGES) { stage = 0; phase ^= 1; }
        }

        // ---------------- epilogue ----------------
        const int flags = g_flags;
        const size_t base_m = (size_t)mtile * BM + wm * 32;
        const int base_n = ntile * BN + wn * 64;
#pragma unroll
        for (int mi = 0; mi < 2; mi++) {
            size_t m0 = base_m + mi * 16 + (lane >> 2);
#pragma unroll
            for (int ni = 0; ni < 8; ni++) {
                int n = base_n + ni * 8 + (lane & 3) * 2;
                __half h0 = __float2half(acc[mi][ni][0]);
                __half h1 = __float2half(acc[mi][ni][1]);
                __half h2 = __float2half(acc[mi][ni][2]);
                __half h3 = __float2half(acc[mi][ni][3]);
                if (flags & 1) {
                    float* yf = (float*)y;
                    *reinterpret_cast<float2*>(yf + m0 * N_DIM + n) =
                        make_float2(__half2float(h0), __half2float(h1));
                    *reinterpret_cast<float2*>(yf + (m0 + 8) * N_DIM + n) =
                        make_float2(__half2float(h2), __half2float(h3));
                } else {
                    __half* yh = (__half*)y;
                    *reinterpret_cast<__half2*>(yh + m0 * N_DIM + n) =
                        __halves2half2(h0, h1);
                    *reinterpret_cast<__half2*>(yh + (m0 + 8) * N_DIM + n) =
                        __halves2half2(h2, h3);
                }
            }
        }
    }

    cluster_sync();
}

// ---------------------------------------------------------------------------
// kernel_launch — inputs by element count: x=33,554,432 w=22,544,384 s=704,512
// ---------------------------------------------------------------------------
typedef CUresult (*EncodeFn)(CUtensorMap*, CUtensorMapDataType, cuuint32_t, void*,
                             const cuuint64_t*, const cuuint64_t*, const cuuint32_t*,
                             const cuuint32_t*, CUtensorMapInterleave, CUtensorMapSwizzle,
                             CUtensorMapL2promotion, CUtensorMapFloatOOBfill);

extern "C" void kernel_launch(void* const* d_in, const int* in_sizes, int n_in,
                              void* d_out, int out_size) {
    const void* x = nullptr; const void* w = nullptr; const void* s = nullptr;
    for (int i = 0; i < n_in; i++) {
        if      (in_sizes[i] == 33554432) x = d_in[i];
        else if (in_sizes[i] == 22544384) w = d_in[i];
        else if (in_sizes[i] == 704512)   s = d_in[i];
    }

    detect_kernel<<<1, 128>>>((const unsigned int*)x, (const unsigned int*)w,
                              (const unsigned int*)s);
    preproc_kernel<<<DQ_BLOCKS + CV_BLOCKS, 256>>>(x, w, s);

    static CUtensorMap tA, tB;
    static bool built = false;
    if (!built) {
        void* encode_raw = nullptr;
        cudaDriverEntryPointQueryResult qr;
        cudaGetDriverEntryPointByVersion("cuTensorMapEncodeTiled", &encode_raw, 12000,
                                         cudaEnableDefault, &qr);
        EncodeFn encode = (EncodeFn)encode_raw;
        void* pa = nullptr; void* pb = nullptr;
        cudaGetSymbolAddress(&pa, g_x);
        cudaGetSymbolAddress(&pb, g_deq);

        cuuint64_t dA[3] = {K_DIM, M_DIM, 1};
        cuuint64_t sA[2] = {K_DIM * 2ull, (cuuint64_t)K_DIM * M_DIM * 2ull};
        cuuint32_t bA[3] = {BK, BM, 1};
        cuuint32_t eS[3] = {1, 1, 1};
        encode(&tA, CU_TENSOR_MAP_DATA_TYPE_FLOAT16, 3, pa, dA, sA, bA, eS,
               CU_TENSOR_MAP_INTERLEAVE_NONE, CU_TENSOR_MAP_SWIZZLE_128B,
               CU_TENSOR_MAP_L2_PROMOTION_L2_128B, CU_TENSOR_MAP_FLOAT_OOB_FILL_NONE);

        cuuint64_t dB[3] = {K_DIM, N_DIM, 1};
        cuuint64_t sB[2] = {K_DIM * 2ull, (cuuint64_t)K_DIM * N_DIM * 2ull};
        cuuint32_t bB[3] = {BK, 64, 1};   // one cooperative slice (64 N-rows)
        encode(&tB, CU_TENSOR_MAP_DATA_TYPE_FLOAT16, 3, pb, dB, sB, bB, eS,
               CU_TENSOR_MAP_INTERLEAVE_NONE, CU_TENSOR_MAP_SWIZZLE_128B,
               CU_TENSOR_MAP_L2_PROMOTION_L2_128B, CU_TENSOR_MAP_FLOAT_OOB_FILL_NONE);

        cudaFuncSetAttribute(gemm_tc, cudaFuncAttributeMaxDynamicSharedMemorySize,
                             SMEM_TOTAL);
        built = true;
    }

    cudaLaunchConfig_t cfg = {};
    cfg.gridDim  = {NTILES, MTILES, 1};   // (86, 64)
    cfg.blockDim = {NTHREADS, 1, 1};
    cfg.dynamicSmemBytes = SMEM_TOTAL;
    cfg.stream = 0;
    cudaLaunchAttribute attrs[1];
    attrs[0].id = cudaLaunchAttributeClusterDimension;
    attrs[0].val.clusterDim = {1, CLUSTER_M, 1};
    cfg.attrs = attrs;
    cfg.numAttrs = 1;
    cudaLaunchKernelEx(&cfg, gemm_tc, tA, tB, d_out);
}